// round 9
// baseline (speedup 1.0000x reference)
#include <cuda_runtime.h>
#include <cuda_pipeline_primitives.h>
#include <mma.h>
#include <math.h>
#include <cstdint>

using namespace nvcuda;

#define BATCHN 16
#define SEQ    512
#define DIMN   2048
#define NH     16
#define HD     128

// Scratch (device globals: allocation-free per harness rules)
__device__ float g_q[BATCHN * NH * SEQ * HD];   // [B,H,T,hd]  (tf32-rounded)
__device__ float g_k[BATCHN * NH * SEQ * HD];
__device__ float g_v[BATCHN * NH * SEQ * HD];
__device__ float g_y[BATCHN * SEQ * DIMN];      // [B,T,C] attention output (tf32-rounded)
__device__ float g_xr[BATCHN * SEQ * DIMN];     // x rounded to tf32
__device__ float g_wq[DIMN * 3 * DIMN];         // Wqkv rounded to tf32
__device__ float g_wo[DIMN * DIMN];             // Wout rounded to tf32

using FragA  = wmma::fragment<wmma::matrix_a, 16, 16, 8, wmma::precision::tf32, wmma::row_major>;
using FragBr = wmma::fragment<wmma::matrix_b, 16, 16, 8, wmma::precision::tf32, wmma::row_major>;
using FragBc = wmma::fragment<wmma::matrix_b, 16, 16, 8, wmma::precision::tf32, wmma::col_major>;
using FragC  = wmma::fragment<wmma::accumulator, 16, 16, 8, float>;

// ============================================================================
// Prep: round fp32 -> tf32 (RNA) once, so all GEMM/attn inner loops can feed
// raw fragments with zero converts (values already exactly tf32).
// ============================================================================
__global__ __launch_bounds__(256) void round_kernel(
    const float4* __restrict__ src, float4* __restrict__ dst, int n4)
{
    int i = blockIdx.x * 256 + threadIdx.x;
    if (i < n4) {
        float4 v = src[i];
        v.x = wmma::__float_to_tf32(v.x);
        v.y = wmma::__float_to_tf32(v.y);
        v.z = wmma::__float_to_tf32(v.z);
        v.w = wmma::__float_to_tf32(v.w);
        dst[i] = v;
    }
}

// ============================================================================
// GEMM core: C[128x128 tile] = A[.,2048] @ B[2048, ldb].
// 3-stage cp.async pipeline, ONE __syncthreads per K-tile.
// 8 warps (4x2), warp tile 32x64. No converts in the loop.
// ============================================================================
#define AS_STRIDE 36
#define BS_STRIDE 132
#define AS_SZ (128 * AS_STRIDE)
#define BS_SZ (32 * BS_STRIDE)
#define STG_SZ (AS_SZ + BS_SZ)                    // floats per stage
#define GEMM_SMEM_BYTES (3 * STG_SZ * 4)          // ~103.5 KB
#define NKT (2048 / 32)

__device__ __forceinline__ void gemm_issue_stage(
    const float* __restrict__ A, const float* __restrict__ Bsrc,
    int ldb, int bm, int bn, int kt, int s, float* dsm)
{
    float* As = dsm + s * STG_SZ;
    float* Bs = dsm + s * STG_SZ + AS_SZ;
    const int tid = threadIdx.x;
#pragma unroll
    for (int i = 0; i < 4; i++) {
        int id = tid + i * 256;
        int r = id >> 3, c = (id & 7) << 2;
        __pipeline_memcpy_async(&As[r * AS_STRIDE + c],
                                A + (size_t)(bm + r) * 2048 + kt * 32 + c, 16);
    }
#pragma unroll
    for (int i = 0; i < 4; i++) {
        int id = tid + i * 256;
        int r = id >> 5, c = (id & 31) << 2;
        __pipeline_memcpy_async(&Bs[r * BS_STRIDE + c],
                                Bsrc + (size_t)(kt * 32 + r) * ldb + bn + c, 16);
    }
    __pipeline_commit();
}

__device__ __forceinline__ void gemm_compute_stage(
    const float* dsm, int s, int wm, int wn, FragC acc[2][4])
{
    const float* as = dsm + s * STG_SZ;
    const float* bs = dsm + s * STG_SZ + AS_SZ;
#pragma unroll
    for (int kk = 0; kk < 4; kk++) {
        FragA a[2];
        FragBr b[4];
#pragma unroll
        for (int mi = 0; mi < 2; mi++)
            wmma::load_matrix_sync(a[mi], as + (wm * 32 + mi * 16) * AS_STRIDE + kk * 8,
                                   AS_STRIDE);
#pragma unroll
        for (int ni = 0; ni < 4; ni++)
            wmma::load_matrix_sync(b[ni], bs + (kk * 8) * BS_STRIDE + wn * 64 + ni * 16,
                                   BS_STRIDE);
#pragma unroll
        for (int mi = 0; mi < 2; mi++)
#pragma unroll
            for (int ni = 0; ni < 4; ni++)
                wmma::mma_sync(acc[mi][ni], a[mi], b[ni], acc[mi][ni]);
    }
}

__device__ __forceinline__ void gemm_tile_compute(
    const float* __restrict__ A, const float* __restrict__ Bsrc,
    int ldb, int bm, int bn, FragC acc[2][4], float* dsm)
{
    const int wid = threadIdx.x >> 5;
    const int wm = wid & 3;
    const int wn = wid >> 2;

#pragma unroll
    for (int mi = 0; mi < 2; mi++)
#pragma unroll
        for (int ni = 0; ni < 4; ni++)
            wmma::fill_fragment(acc[mi][ni], 0.0f);

    // Prologue: 2 stages in flight
    gemm_issue_stage(A, Bsrc, ldb, bm, bn, 0, 0, dsm);
    gemm_issue_stage(A, Bsrc, ldb, bm, bn, 1, 1, dsm);

    int s = 0;      // stage of tile kt
#pragma unroll 1
    for (int kt = 0; kt < NKT - 1; kt++) {
        __pipeline_wait_prior(1);            // tile kt landed (for this thread)
        __syncthreads();                     // ...for all threads; also: all
                                             // warps finished compute(kt-1)
        if (kt + 2 < NKT) {
            int sn = s + 2; if (sn >= 3) sn -= 3;   // slot of kt-1: safe now
            gemm_issue_stage(A, Bsrc, ldb, bm, bn, kt + 2, sn, dsm);
        }
        gemm_compute_stage(dsm, s, wm, wn, acc);
        if (++s == 3) s = 0;
    }
    __pipeline_wait_prior(0);                // final tile
    __syncthreads();
    gemm_compute_stage(dsm, s, wm, wn, acc);
}

// ============================================================================
// QKV GEMM: [8192,2048] @ [2048,6144] -> scatter to g_q/g_k/g_v [B,H,T,hd],
// rounding results to tf32 at the store (so attention can skip converts).
// ============================================================================
__global__ __launch_bounds__(256, 2) void gemm_qkv_kernel()
{
    extern __shared__ __align__(16) float dsm[];
    const int bm = blockIdx.y * 128;
    const int bn = blockIdx.x * 128;
    const int wid = threadIdx.x >> 5;
    const int wm = wid & 3, wn = wid >> 2;

    FragC acc[2][4];
    gemm_tile_compute(g_xr, g_wq, 6144, bm, bn, acc, dsm);

#pragma unroll
    for (int mi = 0; mi < 2; mi++) {
#pragma unroll
        for (int ni = 0; ni < 4; ni++) {
#pragma unroll
            for (int e = 0; e < acc[mi][ni].num_elements; e++)
                acc[mi][ni].x[e] = wmma::__float_to_tf32(acc[mi][ni].x[e]);
            int row = bm + wm * 32 + mi * 16;        // b*512 + t
            int col = bn + wn * 64 + ni * 16;        // sel*2048 + h*128 + d
            int sel = col >> 11;
            int h = (col & 2047) >> 7;
            int d0 = col & 127;
            int b_ = row >> 9;
            int t0 = row & 511;
            float* dst = (sel == 0 ? g_q : (sel == 1 ? g_k : g_v))
                         + ((size_t)(b_ * NH + h) * SEQ + t0) * HD + d0;
            wmma::store_matrix_sync(dst, acc[mi][ni], HD, wmma::mem_row_major);
        }
    }
}

// ============================================================================
// Output GEMM: out = g_y[8192,2048] @ Wout[2048,2048]
// ============================================================================
__global__ __launch_bounds__(256, 2) void gemm_out_kernel(float* __restrict__ C)
{
    extern __shared__ __align__(16) float dsm[];
    const int bm = blockIdx.y * 128;
    const int bn = blockIdx.x * 128;
    const int wid = threadIdx.x >> 5;
    const int wm = wid & 3, wn = wid >> 2;

    FragC acc[2][4];
    gemm_tile_compute(g_y, g_wo, 2048, bm, bn, acc, dsm);

#pragma unroll
    for (int mi = 0; mi < 2; mi++)
#pragma unroll
        for (int ni = 0; ni < 4; ni++) {
            int row = bm + wm * 32 + mi * 16;
            int col = bn + wn * 64 + ni * 16;
            wmma::store_matrix_sync(C + (size_t)row * 2048 + col, acc[mi][ni],
                                    2048, wmma::mem_row_major);
        }
}

// ============================================================================
// RoPE: in-place pairwise rotation of first 16 dims of each head in q and k.
// Rounds rotated values back to tf32 (pass-through dims already rounded).
// ============================================================================
__global__ __launch_bounds__(256) void rope_kernel()
{
    int i = blockIdx.x * 256 + threadIdx.x;
    int d   = i & 7;
    int t   = (i >> 3) & 511;
    int h   = (i >> 12) & 15;
    int b   = (i >> 16) & 15;
    int sel = (i >> 20) & 1;

    float* p = (sel ? g_k : g_q) + ((size_t)(b * NH + h) * SEQ + t) * HD;
    float inv = powf(10000.0f, -(float)d * 0.125f);
    float ang = (float)t * inv;
    float s, c;
    sincosf(ang, &s, &c);
    float x1 = p[d];
    float x2 = p[d + 8];
    p[d]     = wmma::__float_to_tf32(x1 * c - x2 * s);
    p[d + 8] = wmma::__float_to_tf32(x2 * c + x1 * s);
}

// ============================================================================
// Causal attention, single-pass streaming softmax. All operands arrive
// tf32-rounded; P is rounded at the exp store; Y rounded at final write.
// No converts in any wmma loop. (Round-6 passing version, unchanged.)
// ============================================================================
#define SQ_STRIDE 132
#define SS_STRIDE 72
#define ATTN_SMEM_BYTES ((2 * 64 * SQ_STRIDE + 64 * SS_STRIDE + 64) * 4)

__global__ __launch_bounds__(256, 2) void attn_kernel()
{
    extern __shared__ __align__(16) float smem[];
    float* sQ  = smem;                         // 64 x 132
    float* sKV = smem + 64 * SQ_STRIDE;        // 64 x 132
    float* sS  = smem + 2 * 64 * SQ_STRIDE;    // 64 x 72
    float* rowsum = sS + 64 * SS_STRIDE;       // 64

    const int qt = blockIdx.x;    // 0..7
    const int bh = blockIdx.y;    // 0..255
    const int tid = threadIdx.x;
    const int wid = tid >> 5;
    const int lane = tid & 31;
    const int nkt = qt + 1;

    const float* qb = g_q + ((size_t)bh * SEQ + qt * 64) * HD;
    for (int i = tid; i < 2048; i += 256) {
        int r = i >> 5, c = (i & 31) << 2;
        *(float4*)&sQ[r * SQ_STRIDE + c] = *(const float4*)(qb + r * 128 + c);
    }
    if (tid < 64) rowsum[tid] = 0.0f;

    const int owm = wid & 1;
    const int own = wid >> 1;
    FragC o[2][2];
#pragma unroll
    for (int mi = 0; mi < 2; mi++)
#pragma unroll
        for (int ni = 0; ni < 2; ni++)
            wmma::fill_fragment(o[mi][ni], 0.0f);

    const float scl = 0.08838834764831845f;   // 1/sqrt(128)

    for (int kt = 0; kt < nkt; kt++) {
        __syncthreads();
        const float* kb = g_k + ((size_t)bh * SEQ + kt * 64) * HD;
        for (int i = tid; i < 2048; i += 256) {
            int r = i >> 5, c = (i & 31) << 2;
            *(float4*)&sKV[r * SQ_STRIDE + c] = *(const float4*)(kb + r * 128 + c);
        }
        __syncthreads();

        // S = Q K^T
        {
            const int wm = wid & 1;
            const int wn = wid >> 1;
            FragC c[2];
#pragma unroll
            for (int mi = 0; mi < 2; mi++) wmma::fill_fragment(c[mi], 0.0f);
#pragma unroll
            for (int kk = 0; kk < 16; kk++) {
                FragA a[2];
                FragBc b;
#pragma unroll
                for (int mi = 0; mi < 2; mi++)
                    wmma::load_matrix_sync(a[mi],
                        &sQ[(wm * 32 + mi * 16) * SQ_STRIDE + kk * 8], SQ_STRIDE);
                wmma::load_matrix_sync(b, &sKV[(wn * 16) * SQ_STRIDE + kk * 8], SQ_STRIDE);
#pragma unroll
                for (int mi = 0; mi < 2; mi++)
                    wmma::mma_sync(c[mi], a[mi], b, c[mi]);
            }
#pragma unroll
            for (int mi = 0; mi < 2; mi++)
                wmma::store_matrix_sync(&sS[(wm * 32 + mi * 16) * SS_STRIDE + wn * 16],
                                        c[mi], SS_STRIDE, wmma::mem_row_major);
        }
        __syncthreads();

        // Load V tile (overwrites K; K-reads finished above)
        const float* vb = g_v + ((size_t)bh * SEQ + kt * 64) * HD;
        for (int i = tid; i < 2048; i += 256) {
            int r = i >> 5, c = (i & 31) << 2;
            *(float4*)&sKV[r * SQ_STRIDE + c] = *(const float4*)(vb + r * 128 + c);
        }

        // Softmax-exp on this tile (results rounded to tf32 for the PV mma)
        {
            const bool diag = (kt == qt);
#pragma unroll
            for (int rr = 0; rr < 8; rr++) {
                int r = wid * 8 + rr;
                float s0 = sS[r * SS_STRIDE + lane];
                float s1 = sS[r * SS_STRIDE + lane + 32];
                float p0, p1;
                if (diag) {
                    p0 = (lane <= r)      ? __expf(s0 * scl) : 0.0f;
                    p1 = (lane + 32 <= r) ? __expf(s1 * scl) : 0.0f;
                } else {
                    p0 = __expf(s0 * scl);
                    p1 = __expf(s1 * scl);
                }
                p0 = wmma::__float_to_tf32(p0);
                p1 = wmma::__float_to_tf32(p1);
                sS[r * SS_STRIDE + lane]      = p0;
                sS[r * SS_STRIDE + lane + 32] = p1;
                float sum = p0 + p1;
#pragma unroll
                for (int off = 16; off; off >>= 1)
                    sum += __shfl_xor_sync(~0u, sum, off);
                if (lane == 0) rowsum[r] += sum;
            }
        }
        __syncthreads();

        // O += P @ V
#pragma unroll
        for (int kk = 0; kk < 8; kk++) {
            FragA a[2];
            FragBr b[2];
#pragma unroll
            for (int mi = 0; mi < 2; mi++)
                wmma::load_matrix_sync(a[mi],
                    &sS[(owm * 32 + mi * 16) * SS_STRIDE + kk * 8], SS_STRIDE);
#pragma unroll
            for (int ni = 0; ni < 2; ni++)
                wmma::load_matrix_sync(b[ni],
                    &sKV[(kk * 8) * SQ_STRIDE + own * 32 + ni * 16], SQ_STRIDE);
#pragma unroll
            for (int mi = 0; mi < 2; mi++)
#pragma unroll
                for (int ni = 0; ni < 2; ni++)
                    wmma::mma_sync(o[mi][ni], a[mi], b[ni], o[mi][ni]);
        }
    }

    __syncthreads();
#pragma unroll
    for (int mi = 0; mi < 2; mi++)
#pragma unroll
        for (int ni = 0; ni < 2; ni++)
            wmma::store_matrix_sync(
                &sQ[(owm * 32 + mi * 16) * SQ_STRIDE + own * 32 + ni * 16],
                o[mi][ni], SQ_STRIDE, wmma::mem_row_major);
    __syncthreads();

    const int b_ = bh >> 4;
    const int h = bh & 15;
    for (int i = tid; i < 2048; i += 256) {
        int r = i >> 5, c = (i & 31) << 2;
        float inv = 1.0f / rowsum[r];
        float4 v = *(const float4*)&sQ[r * SQ_STRIDE + c];
        v.x = wmma::__float_to_tf32(v.x * inv);
        v.y = wmma::__float_to_tf32(v.y * inv);
        v.z = wmma::__float_to_tf32(v.z * inv);
        v.w = wmma::__float_to_tf32(v.w * inv);
        float* dst = g_y + ((size_t)(b_ * SEQ + qt * 64 + r)) * DIMN + h * HD + c;
        *(float4*)dst = v;
    }
}

// ============================================================================
// Launch
// ============================================================================
extern "C" void kernel_launch(void* const* d_in, const int* in_sizes, int n_in,
                              void* d_out, int out_size)
{
    const float* x    = (const float*)d_in[0];
    const float* Wqkv = (const float*)d_in[1];
    const float* Wout = (const float*)d_in[2];
    float* out = (float*)d_out;

    cudaFuncSetAttribute(gemm_qkv_kernel,
                         cudaFuncAttributeMaxDynamicSharedMemorySize, GEMM_SMEM_BYTES);
    cudaFuncSetAttribute(gemm_out_kernel,
                         cudaFuncAttributeMaxDynamicSharedMemorySize, GEMM_SMEM_BYTES);
    cudaFuncSetAttribute(attn_kernel,
                         cudaFuncAttributeMaxDynamicSharedMemorySize, ATTN_SMEM_BYTES);

    // Resolve device-global addresses for the prep pass
    float *xr_p, *wq_p, *wo_p;
    cudaGetSymbolAddress((void**)&xr_p, g_xr);
    cudaGetSymbolAddress((void**)&wq_p, g_wq);
    cudaGetSymbolAddress((void**)&wo_p, g_wo);

    const int n4_x  = BATCHN * SEQ * DIMN / 4;
    const int n4_wq = DIMN * 3 * DIMN / 4;
    const int n4_wo = DIMN * DIMN / 4;

    // 0. Round all GEMM operands to tf32 once
    round_kernel<<<(n4_x  + 255) / 256, 256>>>((const float4*)x,    (float4*)xr_p, n4_x);
    round_kernel<<<(n4_wq + 255) / 256, 256>>>((const float4*)Wqkv, (float4*)wq_p, n4_wq);
    round_kernel<<<(n4_wo + 255) / 256, 256>>>((const float4*)Wout, (float4*)wo_p, n4_wo);

    // 1. QKV projection with head-transposed scatter (+tf32 rounding)
    gemm_qkv_kernel<<<dim3(48, 64), 256, GEMM_SMEM_BYTES>>>();

    // 2. RoPE in-place on q,k
    rope_kernel<<<(1 << 21) / 256, 256>>>();

    // 3. Causal attention (streaming softmax)
    attn_kernel<<<dim3(8, 256), 256, ATTN_SMEM_BYTES>>>();

    // 4. Output projection
    gemm_out_kernel<<<dim3(16, 64), 256, GEMM_SMEM_BYTES>>>(out);
}